// round 13
// baseline (speedup 1.0000x reference)
#include <cuda_runtime.h>
#include <cuda_bf16.h>
#include <cuda_fp16.h>
#include <cstdint>

#define NB2 128   // persistent blocks in recurrent kernel

// ------------------------------------------------------------------
// Device-global scratch (allocation-free)
// ------------------------------------------------------------------
__device__ float  d_Gx[(size_t)16384 * 4096];      // x@Wx + bias
__device__ __half d_H2h[(size_t)16384 * 1024];     // h fp16 [b*512+t][j] for final FC
__device__ __half d_Hts[(size_t)513 * 32 * 1024];  // h fp16 [t][b][k_perm]
__device__ __half d_xh[(size_t)16384 * 512];       // x converted to fp16
__device__ __half d_Wxh[(size_t)512 * 4096];       // fp16 input weights, k-pair interleaved
__device__ __half d_Wfch[(size_t)1024 * 512];      // fp16 W_fc, k-pair interleaved
__device__ float  d_bx[4096];                      // packed gate biases
__device__ unsigned d_hflag[128];                  // per-block h progress (steps completed)

// ------------------------------------------------------------------
// Helpers
// ------------------------------------------------------------------
__device__ __forceinline__ void mma_f16(float c[4],
                                        unsigned a0, unsigned a1, unsigned a2, unsigned a3,
                                        unsigned b0, unsigned b1) {
    asm volatile(
        "mma.sync.aligned.m16n8k16.row.col.f32.f16.f16.f32 "
        "{%0,%1,%2,%3},{%4,%5,%6,%7},{%8,%9},{%0,%1,%2,%3};"
        : "+f"(c[0]), "+f"(c[1]), "+f"(c[2]), "+f"(c[3])
        : "r"(a0), "r"(a1), "r"(a2), "r"(a3), "r"(b0), "r"(b1));
}

__device__ __forceinline__ void ldsm_x4(unsigned& r0, unsigned& r1,
                                        unsigned& r2, unsigned& r3,
                                        const __half* p) {
    unsigned addr = (unsigned)__cvta_generic_to_shared(p);
    asm volatile("ldmatrix.sync.aligned.m8n8.x4.shared.b16 {%0,%1,%2,%3}, [%4];"
                 : "=r"(r0), "=r"(r1), "=r"(r2), "=r"(r3) : "r"(addr));
}

__device__ __forceinline__ float tanh_a(float x) {
    float y;
    asm("tanh.approx.f32 %0, %1;" : "=f"(y) : "f"(x));
    return y;
}
__device__ __forceinline__ float sigm(float x) {
    return 0.5f * tanh_a(0.5f * x) + 0.5f;
}

// k-permutation of the fp16 h layout (verified in R5-R12)
__device__ __forceinline__ int perm32(int j) {
    int tg = (j & 7) >> 1;
    int a  = (j & 31) >> 4;
    return (j & ~31) + tg * 8 + a * 4 + (j & 1) + 2 * ((j & 15) >> 3);
}

// ------------------------------------------------------------------
// Init: zero h_0 slab and per-block flags (every launch/replay)
// ------------------------------------------------------------------
__global__ void init_kernel() {
    int idx = blockIdx.x * blockDim.x + threadIdx.x;
    if (idx < 16384) ((unsigned*)d_Hts)[idx] = 0u;   // 32768 halves
    if (idx < 128) d_hflag[idx] = 0u;
}

// ------------------------------------------------------------------
// Convert x to fp16 (2 floats / thread)
// ------------------------------------------------------------------
__global__ void xconv_kernel(const float* __restrict__ x) {
    int idx = blockIdx.x * blockDim.x + threadIdx.x;
    float2 v = *(const float2*)(x + 2 * (size_t)idx);
    ((__half2*)d_xh)[idx] = __floats2half2_rn(v.x, v.y);
}

// ------------------------------------------------------------------
// Pack fp16 Wx (k-pair interleaved, N=4096) + gate biases
// ------------------------------------------------------------------
__global__ void pack_kernel(const float* __restrict__ Wf, const float* __restrict__ Wi,
                            const float* __restrict__ Wg, const float* __restrict__ Wo,
                            const float* __restrict__ bf, const float* __restrict__ bi,
                            const float* __restrict__ bg, const float* __restrict__ bo) {
    int idx = blockIdx.x * blockDim.x + threadIdx.x;
    if (idx < 512 * 1024) {
        int k = idx >> 10, j = idx & 1023;
        size_t base = ((size_t)(k >> 1) * 4096) * 2 + (k & 1);
        d_Wxh[base + (size_t)(j) * 2]        = __float2half_rn(Wf[idx]);
        d_Wxh[base + (size_t)(j + 1024) * 2] = __float2half_rn(Wi[idx]);
        d_Wxh[base + (size_t)(j + 2048) * 2] = __float2half_rn(Wg[idx]);
        d_Wxh[base + (size_t)(j + 3072) * 2] = __float2half_rn(Wo[idx]);
    }
    if (idx < 1024) {
        d_bx[idx]        = bf[idx];
        d_bx[idx + 1024] = bi[idx];
        d_bx[idx + 2048] = bg[idx];
        d_bx[idx + 3072] = bo[idx];
    }
}

// ------------------------------------------------------------------
// Pack fp16 W_fc (k-pair interleaved, N=512)
// ------------------------------------------------------------------
__global__ void packfc_kernel(const float* __restrict__ Wfc) {
    int idx = blockIdx.x * blockDim.x + threadIdx.x;   // 0 .. 524287
    int k = idx >> 9, j = idx & 511;
    d_Wfch[(((size_t)(k >> 1) * 512) + j) * 2 + (k & 1)] = __float2half_rn(Wfc[idx]);
}

// ------------------------------------------------------------------
// Generic fp16 GEMM: C[M,N] = A[M,K] @ B[K,N] + bias[N]
// A row-major fp16, B k-pair interleaved fp16, C fp32.
// 128x128x32 tiles, 8 warps; ldmatrix A-frags; register-staged pipeline.
// (Best measured configuration, R12.)
// ------------------------------------------------------------------
__global__ void __launch_bounds__(256) gemm_f16_bias(
    const __half* __restrict__ A, const __half* __restrict__ Bp,
    const float* __restrict__ bias, float* __restrict__ C,
    int M, int N, int K) {
    __shared__ __half sAh[128 * 40];   // 128 rows x 32 halves (+8 pad)
    __shared__ __half sBh[16 * 272];   // 16 k2-rows x 128 cols x 2 (+16 pad)

    const int tid = threadIdx.x;
    const int w = tid >> 5, lane = tid & 31;
    const int g = lane >> 2, tig = lane & 3;
    const int wm = (w >> 2) * 64, wn = (w & 3) * 32;
    const int m0 = blockIdx.y * 128, n0 = blockIdx.x * 128;

    const int rA = wm + (lane & 7) + ((lane >> 3) & 1) * 8;
    const int cA = ((lane >> 4) & 1) * 8;

    const int arr0 = tid >> 2,           aq0 = tid & 3;
    const int arr1 = (tid + 256) >> 2,   aq1 = tid & 3;
    const int bk0 = tid >> 5,            bc0 = tid & 31;
    const int bk1 = (tid + 256) >> 5,    bc1 = tid & 31;

    const __half* gA0 = A + (size_t)(m0 + arr0) * K + aq0 * 8;
    const __half* gA1 = A + (size_t)(m0 + arr1) * K + aq1 * 8;
    const __half* gB0 = Bp + ((size_t)bk0 * N + n0 + bc0 * 4) * 2;
    const __half* gB1 = Bp + ((size_t)bk1 * N + n0 + bc1 * 4) * 2;

    float Cr[4][4][4];
#pragma unroll
    for (int a = 0; a < 4; a++)
#pragma unroll
        for (int b = 0; b < 4; b++)
#pragma unroll
            for (int c = 0; c < 4; c++) Cr[a][b][c] = 0.f;

    const int nk = K / 32;

    uint4 stA0 = *(const uint4*)(gA0);
    uint4 stA1 = *(const uint4*)(gA1);
    uint4 stB0 = *(const uint4*)(gB0);
    uint4 stB1 = *(const uint4*)(gB1);

    for (int kc = 0; kc < nk; kc++) {
        __syncthreads();
        *(uint4*)(sAh + arr0 * 40 + aq0 * 8) = stA0;
        *(uint4*)(sAh + arr1 * 40 + aq1 * 8) = stA1;
        *(uint4*)(sBh + bk0 * 272 + bc0 * 8) = stB0;
        *(uint4*)(sBh + bk1 * 272 + bc1 * 8) = stB1;
        __syncthreads();

        if (kc + 1 < nk) {
            int k0 = (kc + 1) * 32;
            stA0 = *(const uint4*)(gA0 + k0);
            stA1 = *(const uint4*)(gA1 + k0);
            stB0 = *(const uint4*)(gB0 + (size_t)(k0 >> 1) * N * 2);
            stB1 = *(const uint4*)(gB1 + (size_t)(k0 >> 1) * N * 2);
        }

#pragma unroll
        for (int kt = 0; kt < 2; kt++) {
            unsigned bf_[4][2];
#pragma unroll
            for (int nt = 0; nt < 4; nt++) {
                int jc = wn + nt * 8 + g;
                bf_[nt][0] = *(const unsigned*)(sBh + (kt * 8 + tig) * 272 + jc * 2);
                bf_[nt][1] = *(const unsigned*)(sBh + (kt * 8 + tig + 4) * 272 + jc * 2);
            }
#pragma unroll
            for (int mt = 0; mt < 4; mt++) {
                unsigned a0, a1, a2, a3;
                ldsm_x4(a0, a1, a2, a3,
                        sAh + (rA + mt * 16) * 40 + kt * 16 + cA);
#pragma unroll
                for (int nt = 0; nt < 4; nt++)
                    mma_f16(Cr[mt][nt], a0, a1, a2, a3, bf_[nt][0], bf_[nt][1]);
            }
        }
    }

#pragma unroll
    for (int mt = 0; mt < 4; mt++) {
#pragma unroll
        for (int nt = 0; nt < 4; nt++) {
            int row = m0 + wm + mt * 16 + g;
            int col = n0 + wn + nt * 8 + 2 * tig;
            float bx = bias[col], by = bias[col + 1];
            float2 v0 = make_float2(Cr[mt][nt][0] + bx, Cr[mt][nt][1] + by);
            float2 v1 = make_float2(Cr[mt][nt][2] + bx, Cr[mt][nt][3] + by);
            *(float2*)(C + (size_t)row * N + col) = v0;
            *(float2*)(C + (size_t)(row + 8) * N + col) = v1;
        }
    }
}

// ------------------------------------------------------------------
// Persistent recurrent kernel — DATAFLOW version. 128 blocks x 512
// threads. NO global barrier: each block publishes d_hflag[bk] = t+1
// after its state epilogue (st.release.gpu, ordered by the 256-state
// bar.sync — the proven R7 cumulativity pattern). Warp w's h slice
// [64w, 64w+64) is produced by exactly blocks 8w..8w+7, so each warp
// polls ONLY those 8 flags (one 32B sector; all 32 lanes poll lane&7
// -> one coalesced request; its own acquire per lane).
// Intra-block: producers->state via split barrier (bar.arrive 3,512 /
// bar.sync 3,512); state->producers (sPart WAR) via smem counter
// sdone (warps wait sdone >= t before STS; max 1 step of lookahead,
// single sPart buffer stays race-free).
// ------------------------------------------------------------------
__global__ void __launch_bounds__(512) lstm_rec(
    const float* __restrict__ Wf, const float* __restrict__ Wi,
    const float* __restrict__ Wg, const float* __restrict__ Wo) {
    extern __shared__ float sPart[];   // 16 regions x 32 rows x 36 floats
    __shared__ unsigned sdone;

    const int tid = threadIdx.x;
    const int w = tid >> 5, lane = tid & 31;
    const int g = lane >> 2, tig = lane & 3;
    const int kw = w * 64;
    const int bk = blockIdx.x;

    if (tid == 0) sdone = 0u;

    // ---- Preload weights as fp16x2 B-fragments (true k order) ----
    const float* Wp[4] = {Wf, Wi, Wg, Wo};
    unsigned Wr[4][4][2];
#pragma unroll
    for (int kt = 0; kt < 4; kt++) {
#pragma unroll
        for (int nt = 0; nt < 4; nt++) {
            const float* ws = Wp[nt] + (size_t)(512 + kw + kt * 16 + 2 * tig) * 1024 + bk * 8 + g;
            __half2 lo = __floats2half2_rn(__ldg(ws), __ldg(ws + 1024));
            __half2 hi = __floats2half2_rn(__ldg(ws + 8 * 1024), __ldg(ws + 9 * 1024));
            Wr[kt][nt][0] = *(unsigned*)&lo;
            Wr[kt][nt][1] = *(unsigned*)&hi;
        }
    }

    // State-thread mapping (first 256 threads): b = tid/8, uu = tid%8
    const int b_ = (tid >> 3) & 31, uu = tid & 7;
    const bool is_state = tid < 256;
    float creg = 0.f;
    const int j = bk * 8 + uu;
    const int ppos = perm32(j);

    // Incremented pointers
    const __half* hrd = d_Hts + kw + tig * 8;                           // += 32768
    __half* hwr = d_Hts + 32768 + (size_t)b_ * 1024 + ppos;             // += 32768
    const float* gxp = d_Gx + (size_t)(b_ * 512) * 4096 + bk * 8 + uu;  // += 4096
    __half* h2p = d_H2h + (size_t)(b_ * 512) * 1024 + bk * 8 + uu;      // += 1024
    unsigned* prodflag = d_hflag + 8 * w + (lane & 7);   // this warp's producers
    unsigned* myflag = d_hflag + bk;
    const unsigned sda = (unsigned)__cvta_generic_to_shared(&sdone);

    __syncthreads();   // sdone init + weight preload complete

    // Prefetch Gx for step 0
    float gx0 = 0.f, gx1 = 0.f, gx2 = 0.f, gx3 = 0.f;
    if (is_state) {
        gx0 = __ldcs(gxp);
        gx1 = __ldcs(gxp + 1024);
        gx2 = __ldcs(gxp + 2048);
        gx3 = __ldcs(gxp + 3072);
    }

    for (int t = 0; t < 512; t++) {
        // ---- 1. Wait for this warp's 8 producer blocks (flag >= t) ----
        if (t > 0) {
            bool ready = false;
            do {
                unsigned v;
                asm volatile("ld.acquire.gpu.u32 %0, [%1];"
                             : "=r"(v) : "l"(prodflag) : "memory");
                ready = (v >= (unsigned)t);
            } while (!__all_sync(0xffffffffu, ready));
        }

        // ---- 2. Front-batched h loads: 8 x LDG.128 ----
        uint4 V[2][2][2];   // [kb][mt][row g / g+8]
#pragma unroll
        for (int kb = 0; kb < 2; kb++)
#pragma unroll
            for (int mt = 0; mt < 2; mt++) {
                V[kb][mt][0] = __ldcg((const uint4*)(hrd + kb * 32 + (mt * 16 + g) * 1024));
                V[kb][mt][1] = __ldcg((const uint4*)(hrd + kb * 32 + (mt * 16 + g + 8) * 1024));
            }

        // ---- 3. h_t @ Wh_slice (fp16 HMMA, fp32 accum) ----
        float Cr[2][4][4];
#pragma unroll
        for (int mt = 0; mt < 2; mt++)
#pragma unroll
            for (int nt = 0; nt < 4; nt++)
#pragma unroll
                for (int c = 0; c < 4; c++) Cr[mt][nt][c] = 0.f;

#pragma unroll
        for (int kb = 0; kb < 2; kb++) {
#pragma unroll
            for (int mt = 0; mt < 2; mt++) {
                const uint4& v0 = V[kb][mt][0];
                const uint4& v1 = V[kb][mt][1];
#pragma unroll
                for (int nt = 0; nt < 4; nt++)
                    mma_f16(Cr[mt][nt], v0.x, v1.x, v0.y, v1.y,
                            Wr[2 * kb][nt][0], Wr[2 * kb][nt][1]);
#pragma unroll
                for (int nt = 0; nt < 4; nt++)
                    mma_f16(Cr[mt][nt], v0.z, v1.z, v0.w, v1.w,
                            Wr[2 * kb + 1][nt][0], Wr[2 * kb + 1][nt][1]);
            }
        }

        // ---- 4. Wait sPart free (state finished step t-1) ----
        if (t > 0) {
            unsigned v;
            do {
                asm volatile("ld.acquire.cta.shared.u32 %0, [%1];"
                             : "=r"(v) : "r"(sda) : "memory");
            } while (v < (unsigned)t);
        }

        // ---- 5. Write partials: region w, gate-contiguous layout ----
        {
            float* sp = sPart + w * 1152;
#pragma unroll
            for (int mt = 0; mt < 2; mt++) {
#pragma unroll
                for (int nt = 0; nt < 4; nt++) {
                    int row = mt * 16 + g, c = 2 * tig;
                    sp[row * 36 + c * 4 + nt]             = Cr[mt][nt][0];
                    sp[row * 36 + (c + 1) * 4 + nt]       = Cr[mt][nt][1];
                    sp[(row + 8) * 36 + c * 4 + nt]       = Cr[mt][nt][2];
                    sp[(row + 8) * 36 + (c + 1) * 4 + nt] = Cr[mt][nt][3];
                }
            }
        }

        // ---- 6. Producer/consumer barrier + state epilogue ----
        if (is_state) {
            asm volatile("bar.sync 3, 512;" ::: "memory");   // all partials in

            const float4* rp = (const float4*)sPart + (b_ * 9 + uu);
            float4 s0 = rp[0], s1 = rp[288];
#pragma unroll
            for (int r = 2; r < 16; r += 2) {
                float4 a = rp[r * 288], b = rp[(r + 1) * 288];
                s0.x += a.x; s0.y += a.y; s0.z += a.z; s0.w += a.w;
                s1.x += b.x; s1.y += b.y; s1.z += b.z; s1.w += b.w;
            }
            float F = s0.x + s1.x + gx0;
            float I = s0.y + s1.y + gx1;
            float G = s0.z + s1.z + gx2;
            float O = s0.w + s1.w + gx3;
            creg = sigm(F) * creg + sigm(I) * tanh_a(G);
            float h = sigm(O) * tanh_a(creg);

            __half hh = __float2half_rn(h);
            *hwr = hh;
            *h2p = hh;

            // All state threads done (sPart reads + h stores)
            asm volatile("bar.sync 1, 256;" ::: "memory");
            if (tid == 0) {
                asm volatile("st.release.gpu.u32 [%0], %1;"
                             :: "l"(myflag), "r"((unsigned)(t + 1)) : "memory");
                asm volatile("st.release.cta.shared.u32 [%0], %1;"
                             :: "r"(sda), "r"((unsigned)(t + 1)) : "memory");
            }

            // Prefetch Gx for step t+1 (off the critical path)
            gxp += 4096;
            if (t < 511) {
                gx0 = __ldcs(gxp);
                gx1 = __ldcs(gxp + 1024);
                gx2 = __ldcs(gxp + 2048);
                gx3 = __ldcs(gxp + 3072);
            }
        } else {
            asm volatile("bar.arrive 3, 512;" ::: "memory");
        }

        hrd += 32768; hwr += 32768; h2p += 1024;
    }
}

// ------------------------------------------------------------------
// Launch sequence (graph-capturable: kernel launches only)
// ------------------------------------------------------------------
extern "C" void kernel_launch(void* const* d_in, const int* in_sizes, int n_in,
                              void* d_out, int out_size) {
    const float* x    = (const float*)d_in[0];
    const float* W_f  = (const float*)d_in[1];
    const float* b_f  = (const float*)d_in[2];
    const float* W_i  = (const float*)d_in[3];
    const float* b_i  = (const float*)d_in[4];
    const float* W_g  = (const float*)d_in[5];
    const float* b_g  = (const float*)d_in[6];
    const float* W_o  = (const float*)d_in[7];
    const float* b_o  = (const float*)d_in[8];
    const float* W_fc = (const float*)d_in[9];
    const float* b_fc = (const float*)d_in[10];
    float* out = (float*)d_out;

    void *pGx, *pH2h, *pXh, *pWxh, *pWfch, *pbx;
    cudaGetSymbolAddress(&pGx, d_Gx);
    cudaGetSymbolAddress(&pH2h, d_H2h);
    cudaGetSymbolAddress(&pXh, d_xh);
    cudaGetSymbolAddress(&pWxh, d_Wxh);
    cudaGetSymbolAddress(&pWfch, d_Wfch);
    cudaGetSymbolAddress(&pbx, d_bx);

    static bool attr_set = false;
    if (!attr_set) {
        cudaFuncSetAttribute(lstm_rec, cudaFuncAttributeMaxDynamicSharedMemorySize,
                             16 * 1152 * 4);
        attr_set = true;
    }

    init_kernel<<<128, 256>>>();
    xconv_kernel<<<16384, 256>>>(x);
    pack_kernel<<<2048, 256>>>(W_f, W_i, W_g, W_o, b_f, b_i, b_g, b_o);
    packfc_kernel<<<2048, 256>>>(W_fc);

    // Phase 1: Gx = x @ Wx + bx   (fp16 HMMA, M=16384, N=4096, K=512)
    gemm_f16_bias<<<dim3(32, 128), 256>>>(
        (const __half*)pXh, (const __half*)pWxh, (const float*)pbx,
        (float*)pGx, 16384, 4096, 512);

    // Phase 2: recurrence (persistent dataflow, 128 blocks)
    lstm_rec<<<NB2, 512, 16 * 1152 * 4>>>(W_f, W_i, W_g, W_o);

    // Phase 3: out = H2h @ W_fc + b_fc   (fp16 HMMA, M=16384, N=512, K=1024)
    gemm_f16_bias<<<dim3(4, 128), 256>>>(
        (const __half*)pH2h, (const __half*)pWfch, b_fc,
        out, 16384, 512, 1024);
}

// round 14
// speedup vs baseline: 2.9132x; 2.9132x over previous
#include <cuda_runtime.h>
#include <cuda_bf16.h>
#include <cuda_fp16.h>
#include <cstdint>

#define NB2 128   // persistent blocks in recurrent kernel (best measured)

// ------------------------------------------------------------------
// Device-global scratch (allocation-free)
// ------------------------------------------------------------------
__device__ float  d_Gx[(size_t)16384 * 4096];      // x@Wx + bias
__device__ __half d_H2h[(size_t)16384 * 1024];     // h fp16 [b*512+t][j] for final FC
__device__ __half d_Hts[(size_t)513 * 32 * 1024];  // h fp16 [t][b][k_perm]
__device__ __half d_xh[(size_t)16384 * 512];       // x converted to fp16
__device__ __half d_Wxh[(size_t)512 * 4096];       // fp16 input weights, k-pair interleaved
__device__ __half d_Wfch[(size_t)1024 * 512];      // fp16 W_fc, k-pair interleaved
__device__ float  d_bx[4096];                      // packed gate biases
__device__ unsigned d_cnt[512];                    // per-step arrival counters

// ------------------------------------------------------------------
// Helpers
// ------------------------------------------------------------------
__device__ __forceinline__ void mma_f16(float c[4],
                                        unsigned a0, unsigned a1, unsigned a2, unsigned a3,
                                        unsigned b0, unsigned b1) {
    asm volatile(
        "mma.sync.aligned.m16n8k16.row.col.f32.f16.f16.f32 "
        "{%0,%1,%2,%3},{%4,%5,%6,%7},{%8,%9},{%0,%1,%2,%3};"
        : "+f"(c[0]), "+f"(c[1]), "+f"(c[2]), "+f"(c[3])
        : "r"(a0), "r"(a1), "r"(a2), "r"(a3), "r"(b0), "r"(b1));
}

__device__ __forceinline__ void ldsm_x4(unsigned& r0, unsigned& r1,
                                        unsigned& r2, unsigned& r3,
                                        const __half* p) {
    unsigned addr = (unsigned)__cvta_generic_to_shared(p);
    asm volatile("ldmatrix.sync.aligned.m8n8.x4.shared.b16 {%0,%1,%2,%3}, [%4];"
                 : "=r"(r0), "=r"(r1), "=r"(r2), "=r"(r3) : "r"(addr));
}

__device__ __forceinline__ float tanh_a(float x) {
    float y;
    asm("tanh.approx.f32 %0, %1;" : "=f"(y) : "f"(x));
    return y;
}
__device__ __forceinline__ float sigm(float x) {
    return 0.5f * tanh_a(0.5f * x) + 0.5f;
}

// k-permutation of the fp16 h layout (verified in R5-R13)
__device__ __forceinline__ int perm32(int j) {
    int tg = (j & 7) >> 1;
    int a  = (j & 31) >> 4;
    return (j & ~31) + tg * 8 + a * 4 + (j & 1) + 2 * ((j & 15) >> 3);
}

// ------------------------------------------------------------------
// Fused prep: h_0 zero + counters + x->fp16 + Wx pack + W_fc pack.
// Grid 16384 x 256 covers the largest task (x conversion).
// ------------------------------------------------------------------
__global__ void prep_kernel(const float* __restrict__ x,
                            const float* __restrict__ Wf, const float* __restrict__ Wi,
                            const float* __restrict__ Wg, const float* __restrict__ Wo,
                            const float* __restrict__ bf, const float* __restrict__ bi,
                            const float* __restrict__ bg, const float* __restrict__ bo,
                            const float* __restrict__ Wfc) {
    int idx = blockIdx.x * blockDim.x + threadIdx.x;

    // x -> fp16 (4,194,304 half2 elements)
    {
        float2 v = *(const float2*)(x + 2 * (size_t)idx);
        ((__half2*)d_xh)[idx] = __floats2half2_rn(v.x, v.y);
    }
    // Wx pack (524,288 elements), k-pair interleaved
    if (idx < 512 * 1024) {
        int k = idx >> 10, j = idx & 1023;
        size_t base = ((size_t)(k >> 1) * 4096) * 2 + (k & 1);
        d_Wxh[base + (size_t)(j) * 2]        = __float2half_rn(Wf[idx]);
        d_Wxh[base + (size_t)(j + 1024) * 2] = __float2half_rn(Wi[idx]);
        d_Wxh[base + (size_t)(j + 2048) * 2] = __float2half_rn(Wg[idx]);
        d_Wxh[base + (size_t)(j + 3072) * 2] = __float2half_rn(Wo[idx]);
    }
    // W_fc pack (524,288 elements)
    if (idx < 1024 * 512) {
        int k = idx >> 9, j = idx & 511;
        d_Wfch[(((size_t)(k >> 1) * 512) + j) * 2 + (k & 1)] = __float2half_rn(Wfc[idx]);
    }
    // biases
    if (idx < 1024) {
        d_bx[idx]        = bf[idx];
        d_bx[idx + 1024] = bi[idx];
        d_bx[idx + 2048] = bg[idx];
        d_bx[idx + 3072] = bo[idx];
    }
    // h_0 zero + counters
    if (idx < 16384) ((unsigned*)d_Hts)[idx] = 0u;
    if (idx < 512) d_cnt[idx] = 0u;
}

// ------------------------------------------------------------------
// Generic fp16 GEMM: C[M,N] = A[M,K] @ B[K,N] + bias[N]
// A row-major fp16, B k-pair interleaved fp16, C fp32.
// 128x128x32 tiles, 8 warps; ldmatrix A-frags; register-staged pipeline.
// (Best measured configuration, R12.)
// ------------------------------------------------------------------
__global__ void __launch_bounds__(256) gemm_f16_bias(
    const __half* __restrict__ A, const __half* __restrict__ Bp,
    const float* __restrict__ bias, float* __restrict__ C,
    int M, int N, int K) {
    __shared__ __half sAh[128 * 40];   // 128 rows x 32 halves (+8 pad)
    __shared__ __half sBh[16 * 272];   // 16 k2-rows x 128 cols x 2 (+16 pad)

    const int tid = threadIdx.x;
    const int w = tid >> 5, lane = tid & 31;
    const int g = lane >> 2, tig = lane & 3;
    const int wm = (w >> 2) * 64, wn = (w & 3) * 32;
    const int m0 = blockIdx.y * 128, n0 = blockIdx.x * 128;

    const int rA = wm + (lane & 7) + ((lane >> 3) & 1) * 8;
    const int cA = ((lane >> 4) & 1) * 8;

    const int arr0 = tid >> 2,           aq0 = tid & 3;
    const int arr1 = (tid + 256) >> 2,   aq1 = tid & 3;
    const int bk0 = tid >> 5,            bc0 = tid & 31;
    const int bk1 = (tid + 256) >> 5,    bc1 = tid & 31;

    const __half* gA0 = A + (size_t)(m0 + arr0) * K + aq0 * 8;
    const __half* gA1 = A + (size_t)(m0 + arr1) * K + aq1 * 8;
    const __half* gB0 = Bp + ((size_t)bk0 * N + n0 + bc0 * 4) * 2;
    const __half* gB1 = Bp + ((size_t)bk1 * N + n0 + bc1 * 4) * 2;

    float Cr[4][4][4];
#pragma unroll
    for (int a = 0; a < 4; a++)
#pragma unroll
        for (int b = 0; b < 4; b++)
#pragma unroll
            for (int c = 0; c < 4; c++) Cr[a][b][c] = 0.f;

    const int nk = K / 32;

    uint4 stA0 = *(const uint4*)(gA0);
    uint4 stA1 = *(const uint4*)(gA1);
    uint4 stB0 = *(const uint4*)(gB0);
    uint4 stB1 = *(const uint4*)(gB1);

    for (int kc = 0; kc < nk; kc++) {
        __syncthreads();
        *(uint4*)(sAh + arr0 * 40 + aq0 * 8) = stA0;
        *(uint4*)(sAh + arr1 * 40 + aq1 * 8) = stA1;
        *(uint4*)(sBh + bk0 * 272 + bc0 * 8) = stB0;
        *(uint4*)(sBh + bk1 * 272 + bc1 * 8) = stB1;
        __syncthreads();

        if (kc + 1 < nk) {
            int k0 = (kc + 1) * 32;
            stA0 = *(const uint4*)(gA0 + k0);
            stA1 = *(const uint4*)(gA1 + k0);
            stB0 = *(const uint4*)(gB0 + (size_t)(k0 >> 1) * N * 2);
            stB1 = *(const uint4*)(gB1 + (size_t)(k0 >> 1) * N * 2);
        }

#pragma unroll
        for (int kt = 0; kt < 2; kt++) {
            unsigned bf_[4][2];
#pragma unroll
            for (int nt = 0; nt < 4; nt++) {
                int jc = wn + nt * 8 + g;
                bf_[nt][0] = *(const unsigned*)(sBh + (kt * 8 + tig) * 272 + jc * 2);
                bf_[nt][1] = *(const unsigned*)(sBh + (kt * 8 + tig + 4) * 272 + jc * 2);
            }
#pragma unroll
            for (int mt = 0; mt < 4; mt++) {
                unsigned a0, a1, a2, a3;
                ldsm_x4(a0, a1, a2, a3,
                        sAh + (rA + mt * 16) * 40 + kt * 16 + cA);
#pragma unroll
                for (int nt = 0; nt < 4; nt++)
                    mma_f16(Cr[mt][nt], a0, a1, a2, a3, bf_[nt][0], bf_[nt][1]);
            }
        }
    }

#pragma unroll
    for (int mt = 0; mt < 4; mt++) {
#pragma unroll
        for (int nt = 0; nt < 4; nt++) {
            int row = m0 + wm + mt * 16 + g;
            int col = n0 + wn + nt * 8 + 2 * tig;
            float bx = bias[col], by = bias[col + 1];
            float2 v0 = make_float2(Cr[mt][nt][0] + bx, Cr[mt][nt][1] + by);
            float2 v1 = make_float2(Cr[mt][nt][2] + bx, Cr[mt][nt][3] + by);
            *(float2*)(C + (size_t)row * N + col) = v0;
            *(float2*)(C + (size_t)(row + 8) * N + col) = v1;
        }
    }
}

// ------------------------------------------------------------------
// Persistent recurrent kernel. 128 blocks x 512 threads (16 warps).
// Structure = R12 (best measured, 1922us). Two micro-surgeries:
//  (a) post-STS barrier split: producer warps bar.arrive 3,512 and go
//      straight to the sflag poll; state warps bar.sync 3,512. Safe:
//      producers can't overwrite sPart until sflag=t+1, published only
//      after the state-only bar.sync 1,256 (reduce reads done).
//  (b) the d_H2h store moves AFTER the release — st.release.gpu drains
//      all prior stores, and d_H2h is only read by phase 3 (ordered by
//      the kernel boundary), so its drain was pure critical-path waste.
// ------------------------------------------------------------------
__global__ void __launch_bounds__(512) lstm_rec(
    const float* __restrict__ Wf, const float* __restrict__ Wi,
    const float* __restrict__ Wg, const float* __restrict__ Wo) {
    extern __shared__ float sPart[];   // 16 regions x 32 rows x 36 floats
    __shared__ unsigned sflag;

    const int tid = threadIdx.x;
    const int w = tid >> 5, lane = tid & 31;
    const int g = lane >> 2, tig = lane & 3;
    const int kw = w * 64;
    const int bk = blockIdx.x;

    if (tid == 0) sflag = 0u;

    // ---- Preload weights as fp16x2 B-fragments (true k order) ----
    const float* Wp[4] = {Wf, Wi, Wg, Wo};
    unsigned Wr[4][4][2];
#pragma unroll
    for (int kt = 0; kt < 4; kt++) {
#pragma unroll
        for (int nt = 0; nt < 4; nt++) {
            const float* ws = Wp[nt] + (size_t)(512 + kw + kt * 16 + 2 * tig) * 1024 + bk * 8 + g;
            __half2 lo = __floats2half2_rn(__ldg(ws), __ldg(ws + 1024));
            __half2 hi = __floats2half2_rn(__ldg(ws + 8 * 1024), __ldg(ws + 9 * 1024));
            Wr[kt][nt][0] = *(unsigned*)&lo;
            Wr[kt][nt][1] = *(unsigned*)&hi;
        }
    }

    // State-thread mapping (first 256 threads): b = tid/8, uu = tid%8
    const int b_ = (tid >> 3) & 31, uu = tid & 7;
    const bool is_state = tid < 256;
    float creg = 0.f;
    const int j = bk * 8 + uu;
    const int ppos = perm32(j);

    // Incremented pointers
    const __half* hrd = d_Hts + kw + tig * 8;                           // += 32768
    __half* hwr = d_Hts + 32768 + (size_t)b_ * 1024 + ppos;             // += 32768
    const float* gxp = d_Gx + (size_t)(b_ * 512) * 4096 + bk * 8 + uu;  // += 4096
    __half* h2p = d_H2h + (size_t)(b_ * 512) * 1024 + bk * 8 + uu;      // += 1024
    unsigned* cntp = d_cnt;                                              // += 1
    const unsigned sfa = (unsigned)__cvta_generic_to_shared(&sflag);

    __syncthreads();   // sflag init + weight preload complete

    // Prefetch Gx for step 0
    float gx0 = 0.f, gx1 = 0.f, gx2 = 0.f, gx3 = 0.f;
    if (is_state) {
        gx0 = __ldcs(gxp);
        gx1 = __ldcs(gxp + 1024);
        gx2 = __ldcs(gxp + 2048);
        gx3 = __ldcs(gxp + 3072);
    }

    for (int t = 0; t < 512; t++) {
        // ---- Per-warp wait on the block's release flag ----
        if (t > 0) {
            unsigned v;
            do {
                asm volatile("ld.acquire.cta.shared.u32 %0, [%1];"
                             : "=r"(v) : "r"(sfa) : "memory");
            } while (v < (unsigned)t);
        }

        // ---- Front-batched h loads: 8 x LDG.128 (max MLP) ----
        uint4 V[2][2][2];   // [kb][mt][row g / g+8]
#pragma unroll
        for (int kb = 0; kb < 2; kb++)
#pragma unroll
            for (int mt = 0; mt < 2; mt++) {
                V[kb][mt][0] = __ldcg((const uint4*)(hrd + kb * 32 + (mt * 16 + g) * 1024));
                V[kb][mt][1] = __ldcg((const uint4*)(hrd + kb * 32 + (mt * 16 + g + 8) * 1024));
            }

        // ---- h_t @ Wh_slice (fp16 HMMA, fp32 accum) ----
        float Cr[2][4][4];
#pragma unroll
        for (int mt = 0; mt < 2; mt++)
#pragma unroll
            for (int nt = 0; nt < 4; nt++)
#pragma unroll
                for (int c = 0; c < 4; c++) Cr[mt][nt][c] = 0.f;

#pragma unroll
        for (int kb = 0; kb < 2; kb++) {
#pragma unroll
            for (int mt = 0; mt < 2; mt++) {
                const uint4& v0 = V[kb][mt][0];
                const uint4& v1 = V[kb][mt][1];
#pragma unroll
                for (int nt = 0; nt < 4; nt++)
                    mma_f16(Cr[mt][nt], v0.x, v1.x, v0.y, v1.y,
                            Wr[2 * kb][nt][0], Wr[2 * kb][nt][1]);
#pragma unroll
                for (int nt = 0; nt < 4; nt++)
                    mma_f16(Cr[mt][nt], v0.z, v1.z, v0.w, v1.w,
                            Wr[2 * kb + 1][nt][0], Wr[2 * kb + 1][nt][1]);
            }
        }

        // ---- Write partials: region w, gate-contiguous layout ----
        {
            float* sp = sPart + w * 1152;
#pragma unroll
            for (int mt = 0; mt < 2; mt++) {
#pragma unroll
                for (int nt = 0; nt < 4; nt++) {
                    int row = mt * 16 + g, c = 2 * tig;
                    sp[row * 36 + c * 4 + nt]             = Cr[mt][nt][0];
                    sp[row * 36 + (c + 1) * 4 + nt]       = Cr[mt][nt][1];
                    sp[(row + 8) * 36 + c * 4 + nt]       = Cr[mt][nt][2];
                    sp[(row + 8) * 36 + (c + 1) * 4 + nt] = Cr[mt][nt][3];
                }
            }
        }

        // ---- Split barrier + state epilogue + arrival + release ----
        if (is_state) {
            asm volatile("bar.sync 3, 512;" ::: "memory");   // all partials in

            const float4* rp = (const float4*)sPart + (b_ * 9 + uu);
            float4 s0 = rp[0], s1 = rp[288];
#pragma unroll
            for (int r = 2; r < 16; r += 2) {
                float4 a = rp[r * 288], b = rp[(r + 1) * 288];
                s0.x += a.x; s0.y += a.y; s0.z += a.z; s0.w += a.w;
                s1.x += b.x; s1.y += b.y; s1.z += b.z; s1.w += b.w;
            }
            float F = s0.x + s1.x + gx0;
            float I = s0.y + s1.y + gx1;
            float G = s0.z + s1.z + gx2;
            float O = s0.w + s1.w + gx3;
            creg = sigm(F) * creg + sigm(I) * tanh_a(G);
            float h = sigm(O) * tanh_a(creg);

            __half hh = __float2half_rn(h);
            *hwr = hh;

            // All state threads done (sPart reads + h store) -> arrive
            asm volatile("bar.sync 1, 256;" ::: "memory");
            if (tid == 0) {
                unsigned ret;
                asm volatile("atom.acq_rel.gpu.add.u32 %0, [%1], %2;"
                             : "=r"(ret) : "l"(cntp), "r"(1u) : "memory");
                if (ret + 1u < NB2) {
                    unsigned v;
                    do {
                        asm volatile("ld.acquire.gpu.u32 %0, [%1];"
                                     : "=r"(v) : "l"(cntp) : "memory");
                    } while (v < NB2);
                }
                asm volatile("st.release.cta.shared.u32 [%0], %1;"
                             :: "r"(sfa), "r"((unsigned)(t + 1)) : "memory");
            }

            // Off the release-drain set: FC-layout h store + Gx prefetch
            *h2p = hh;
            gxp += 4096;
            if (t < 511) {
                gx0 = __ldcs(gxp);
                gx1 = __ldcs(gxp + 1024);
                gx2 = __ldcs(gxp + 2048);
                gx3 = __ldcs(gxp + 3072);
            }
        } else {
            asm volatile("bar.arrive 3, 512;" ::: "memory");
        }

        hrd += 32768; hwr += 32768; h2p += 1024; cntp += 1;
    }
}

// ------------------------------------------------------------------
// Launch sequence (graph-capturable: kernel launches only)
// ------------------------------------------------------------------
extern "C" void kernel_launch(void* const* d_in, const int* in_sizes, int n_in,
                              void* d_out, int out_size) {
    const float* x    = (const float*)d_in[0];
    const float* W_f  = (const float*)d_in[1];
    const float* b_f  = (const float*)d_in[2];
    const float* W_i  = (const float*)d_in[3];
    const float* b_i  = (const float*)d_in[4];
    const float* W_g  = (const float*)d_in[5];
    const float* b_g  = (const float*)d_in[6];
    const float* W_o  = (const float*)d_in[7];
    const float* b_o  = (const float*)d_in[8];
    const float* W_fc = (const float*)d_in[9];
    const float* b_fc = (const float*)d_in[10];
    float* out = (float*)d_out;

    void *pGx, *pH2h, *pXh, *pWxh, *pWfch, *pbx;
    cudaGetSymbolAddress(&pGx, d_Gx);
    cudaGetSymbolAddress(&pH2h, d_H2h);
    cudaGetSymbolAddress(&pXh, d_xh);
    cudaGetSymbolAddress(&pWxh, d_Wxh);
    cudaGetSymbolAddress(&pWfch, d_Wfch);
    cudaGetSymbolAddress(&pbx, d_bx);

    static bool attr_set = false;
    if (!attr_set) {
        cudaFuncSetAttribute(lstm_rec, cudaFuncAttributeMaxDynamicSharedMemorySize,
                             16 * 1152 * 4);
        attr_set = true;
    }

    // Fused prep: h0/counters + x->fp16 + Wx/W_fc/bias packing
    prep_kernel<<<16384, 256>>>(x, W_f, W_i, W_g, W_o,
                                b_f, b_i, b_g, b_o, W_fc);

    // Phase 1: Gx = x @ Wx + bx   (fp16 HMMA, M=16384, N=4096, K=512)
    gemm_f16_bias<<<dim3(32, 128), 256>>>(
        (const __half*)pXh, (const __half*)pWxh, (const float*)pbx,
        (float*)pGx, 16384, 4096, 512);

    // Phase 2: recurrence (persistent, 128 blocks)
    lstm_rec<<<NB2, 512, 16 * 1152 * 4>>>(W_f, W_i, W_g, W_o);

    // Phase 3: out = H2h @ W_fc + b_fc   (fp16 HMMA, M=16384, N=512, K=1024)
    gemm_f16_bias<<<dim3(4, 128), 256>>>(
        (const __half*)pH2h, (const __half*)pWfch, b_fc,
        out, 16384, 512, 1024);
}

// round 15
// speedup vs baseline: 2.9573x; 1.0151x over previous
#include <cuda_runtime.h>
#include <cuda_bf16.h>
#include <cuda_fp16.h>
#include <cstdint>

#define NB2 128   // persistent blocks in recurrent kernel (best measured)

// ------------------------------------------------------------------
// Device-global scratch (allocation-free)
// ------------------------------------------------------------------
__device__ float  d_Gx[(size_t)16384 * 4096];      // x@Wx + bias
__device__ __half d_H2h[(size_t)16384 * 1024];     // h fp16 [b*512+t][j] for final FC
__device__ __half d_Hts[(size_t)513 * 32 * 1024];  // h fp16 [t][b][k_perm]
__device__ __half d_xh[(size_t)16384 * 512];       // x converted to fp16
__device__ __half d_Wxh[(size_t)512 * 4096];       // fp16 input weights, k-pair interleaved
__device__ __half d_Wfch[(size_t)1024 * 512];      // fp16 W_fc, k-pair interleaved
__device__ float  d_bx[4096];                      // packed gate biases
__device__ unsigned d_cnt[512];                    // per-step arrival counters

// ------------------------------------------------------------------
// Helpers
// ------------------------------------------------------------------
__device__ __forceinline__ void mma_f16(float c[4],
                                        unsigned a0, unsigned a1, unsigned a2, unsigned a3,
                                        unsigned b0, unsigned b1) {
    asm volatile(
        "mma.sync.aligned.m16n8k16.row.col.f32.f16.f16.f32 "
        "{%0,%1,%2,%3},{%4,%5,%6,%7},{%8,%9},{%0,%1,%2,%3};"
        : "+f"(c[0]), "+f"(c[1]), "+f"(c[2]), "+f"(c[3])
        : "r"(a0), "r"(a1), "r"(a2), "r"(a3), "r"(b0), "r"(b1));
}

__device__ __forceinline__ void ldsm_x4(unsigned& r0, unsigned& r1,
                                        unsigned& r2, unsigned& r3,
                                        const __half* p) {
    unsigned addr = (unsigned)__cvta_generic_to_shared(p);
    asm volatile("ldmatrix.sync.aligned.m8n8.x4.shared.b16 {%0,%1,%2,%3}, [%4];"
                 : "=r"(r0), "=r"(r1), "=r"(r2), "=r"(r3) : "r"(addr));
}

__device__ __forceinline__ void cpa16(__half* s, const __half* g) {
    unsigned sa = (unsigned)__cvta_generic_to_shared(s);
    asm volatile("cp.async.ca.shared.global [%0], [%1], 16;" :: "r"(sa), "l"(g));
}

__device__ __forceinline__ float tanh_a(float x) {
    float y;
    asm("tanh.approx.f32 %0, %1;" : "=f"(y) : "f"(x));
    return y;
}
__device__ __forceinline__ float sigm(float x) {
    return 0.5f * tanh_a(0.5f * x) + 0.5f;
}

// k-permutation of the fp16 h layout (verified in R5-R14)
__device__ __forceinline__ int perm32(int j) {
    int tg = (j & 7) >> 1;
    int a  = (j & 31) >> 4;
    return (j & ~31) + tg * 8 + a * 4 + (j & 1) + 2 * ((j & 15) >> 3);
}

// ------------------------------------------------------------------
// Fused prep: h_0 zero + counters + x->fp16 + Wx pack + W_fc pack.
// ------------------------------------------------------------------
__global__ void prep_kernel(const float* __restrict__ x,
                            const float* __restrict__ Wf, const float* __restrict__ Wi,
                            const float* __restrict__ Wg, const float* __restrict__ Wo,
                            const float* __restrict__ bf, const float* __restrict__ bi,
                            const float* __restrict__ bg, const float* __restrict__ bo,
                            const float* __restrict__ Wfc) {
    int idx = blockIdx.x * blockDim.x + threadIdx.x;

    {   // x -> fp16 (4,194,304 half2 elements)
        float2 v = *(const float2*)(x + 2 * (size_t)idx);
        ((__half2*)d_xh)[idx] = __floats2half2_rn(v.x, v.y);
    }
    if (idx < 512 * 1024) {   // Wx pack, k-pair interleaved
        int k = idx >> 10, j = idx & 1023;
        size_t base = ((size_t)(k >> 1) * 4096) * 2 + (k & 1);
        d_Wxh[base + (size_t)(j) * 2]        = __float2half_rn(Wf[idx]);
        d_Wxh[base + (size_t)(j + 1024) * 2] = __float2half_rn(Wi[idx]);
        d_Wxh[base + (size_t)(j + 2048) * 2] = __float2half_rn(Wg[idx]);
        d_Wxh[base + (size_t)(j + 3072) * 2] = __float2half_rn(Wo[idx]);
    }
    if (idx < 1024 * 512) {   // W_fc pack
        int k = idx >> 9, j = idx & 511;
        d_Wfch[(((size_t)(k >> 1) * 512) + j) * 2 + (k & 1)] = __float2half_rn(Wfc[idx]);
    }
    if (idx < 1024) {
        d_bx[idx]        = bf[idx];
        d_bx[idx + 1024] = bi[idx];
        d_bx[idx + 2048] = bg[idx];
        d_bx[idx + 3072] = bo[idx];
    }
    if (idx < 16384) ((unsigned*)d_Hts)[idx] = 0u;
    if (idx < 512) d_cnt[idx] = 0u;
}

// ------------------------------------------------------------------
// Generic fp16 GEMM: C[M,N] = A[M,K] @ B[K,N] + bias[N]
// A row-major fp16, B k-pair interleaved fp16, C fp32.
// 128x128x32 tiles, 8 warps; ldmatrix A-frags.
// NEW: 3-stage cp.async ring, ONE syncthreads per k-iteration.
// Ordering: wait(stage kc) -> sync (kc visible AND compute(kc-1)
// done by ALL warps) -> issue(kc+2) (overwrites stage (kc-1)%3,
// now safe) -> compute(kc).
// Dynamic smem: 3 x (10240 + 8704) = 56832 bytes.
// ------------------------------------------------------------------
#define GEMM_SMEM (3 * (5120 + 4352) * 2)

__global__ void __launch_bounds__(256) gemm_f16_bias(
    const __half* __restrict__ A, const __half* __restrict__ Bp,
    const float* __restrict__ bias, float* __restrict__ C,
    int M, int N, int K) {
    extern __shared__ __half sm[];
    // stages: A at sm + s*5120 ; B at sm + 15360 + s*4352
    const int tid = threadIdx.x;
    const int w = tid >> 5, lane = tid & 31;
    const int g = lane >> 2, tig = lane & 3;
    const int wm = (w >> 2) * 64, wn = (w & 3) * 32;
    const int m0 = blockIdx.y * 128, n0 = blockIdx.x * 128;

    const int rA = wm + (lane & 7) + ((lane >> 3) & 1) * 8;
    const int cA = ((lane >> 4) & 1) * 8;

    const int arr0 = tid >> 2,           aq0 = tid & 3;
    const int arr1 = (tid + 256) >> 2,   aq1 = tid & 3;
    const int bk0 = tid >> 5,            bc0 = tid & 31;
    const int bk1 = (tid + 256) >> 5,    bc1 = tid & 31;

    const __half* gA0 = A + (size_t)(m0 + arr0) * K + aq0 * 8;
    const __half* gA1 = A + (size_t)(m0 + arr1) * K + aq1 * 8;
    const __half* gB0 = Bp + ((size_t)bk0 * N + n0 + bc0 * 4) * 2;
    const __half* gB1 = Bp + ((size_t)bk1 * N + n0 + bc1 * 4) * 2;

    float Cr[4][4][4];
#pragma unroll
    for (int a = 0; a < 4; a++)
#pragma unroll
        for (int b = 0; b < 4; b++)
#pragma unroll
            for (int c = 0; c < 4; c++) Cr[a][b][c] = 0.f;

    const int nk = K / 32;

    // issue stage kc into ring slot kc%3
    auto issue = [&](int kc) {
        int s = kc % 3;
        __half* sAs = sm + s * 5120;
        __half* sBs = sm + 15360 + s * 4352;
        int k0 = kc * 32;
        cpa16(sAs + arr0 * 40 + aq0 * 8, gA0 + k0);
        cpa16(sAs + arr1 * 40 + aq1 * 8, gA1 + k0);
        cpa16(sBs + bk0 * 272 + bc0 * 8, gB0 + (size_t)(k0 >> 1) * N * 2);
        cpa16(sBs + bk1 * 272 + bc1 * 8, gB1 + (size_t)(k0 >> 1) * N * 2);
        asm volatile("cp.async.commit_group;" ::: "memory");
    };

    issue(0);
    if (nk > 1) issue(1);

    for (int kc = 0; kc < nk; kc++) {
        if (kc + 1 < nk) {
            asm volatile("cp.async.wait_group 1;" ::: "memory");
        } else {
            asm volatile("cp.async.wait_group 0;" ::: "memory");
        }
        __syncthreads();
        if (kc + 2 < nk) issue(kc + 2);

        const int s = kc % 3;
        const __half* sAs = sm + s * 5120;
        const __half* sBs = sm + 15360 + s * 4352;

#pragma unroll
        for (int kt = 0; kt < 2; kt++) {
            unsigned bf_[4][2];
#pragma unroll
            for (int nt = 0; nt < 4; nt++) {
                int jc = wn + nt * 8 + g;
                bf_[nt][0] = *(const unsigned*)(sBs + (kt * 8 + tig) * 272 + jc * 2);
                bf_[nt][1] = *(const unsigned*)(sBs + (kt * 8 + tig + 4) * 272 + jc * 2);
            }
#pragma unroll
            for (int mt = 0; mt < 4; mt++) {
                unsigned a0, a1, a2, a3;
                ldsm_x4(a0, a1, a2, a3,
                        sAs + (rA + mt * 16) * 40 + kt * 16 + cA);
#pragma unroll
                for (int nt = 0; nt < 4; nt++)
                    mma_f16(Cr[mt][nt], a0, a1, a2, a3, bf_[nt][0], bf_[nt][1]);
            }
        }
    }

#pragma unroll
    for (int mt = 0; mt < 4; mt++) {
#pragma unroll
        for (int nt = 0; nt < 4; nt++) {
            int row = m0 + wm + mt * 16 + g;
            int col = n0 + wn + nt * 8 + 2 * tig;
            float bx = bias[col], by = bias[col + 1];
            float2 v0 = make_float2(Cr[mt][nt][0] + bx, Cr[mt][nt][1] + by);
            float2 v1 = make_float2(Cr[mt][nt][2] + bx, Cr[mt][nt][3] + by);
            *(float2*)(C + (size_t)row * N + col) = v0;
            *(float2*)(C + (size_t)(row + 8) * N + col) = v1;
        }
    }
}

// ------------------------------------------------------------------
// Persistent recurrent kernel. 128 blocks x 512 threads (16 warps).
// EXACT R14 structure (best measured, 1907us): smem-flag release,
// split post-STS barrier (producers bar.arrive), tid0-only global
// atomic + counter poll, d_H2h store + Gx prefetch off the release
// drain set, tanh.approx gates, fp16 HMMA + k_perm h layout.
// ------------------------------------------------------------------
__global__ void __launch_bounds__(512) lstm_rec(
    const float* __restrict__ Wf, const float* __restrict__ Wi,
    const float* __restrict__ Wg, const float* __restrict__ Wo) {
    extern __shared__ float sPart[];   // 16 regions x 32 rows x 36 floats
    __shared__ unsigned sflag;

    const int tid = threadIdx.x;
    const int w = tid >> 5, lane = tid & 31;
    const int g = lane >> 2, tig = lane & 3;
    const int kw = w * 64;
    const int bk = blockIdx.x;

    if (tid == 0) sflag = 0u;

    // ---- Preload weights as fp16x2 B-fragments (true k order) ----
    const float* Wp[4] = {Wf, Wi, Wg, Wo};
    unsigned Wr[4][4][2];
#pragma unroll
    for (int kt = 0; kt < 4; kt++) {
#pragma unroll
        for (int nt = 0; nt < 4; nt++) {
            const float* ws = Wp[nt] + (size_t)(512 + kw + kt * 16 + 2 * tig) * 1024 + bk * 8 + g;
            __half2 lo = __floats2half2_rn(__ldg(ws), __ldg(ws + 1024));
            __half2 hi = __floats2half2_rn(__ldg(ws + 8 * 1024), __ldg(ws + 9 * 1024));
            Wr[kt][nt][0] = *(unsigned*)&lo;
            Wr[kt][nt][1] = *(unsigned*)&hi;
        }
    }

    // State-thread mapping (first 256 threads): b = tid/8, uu = tid%8
    const int b_ = (tid >> 3) & 31, uu = tid & 7;
    const bool is_state = tid < 256;
    float creg = 0.f;
    const int j = bk * 8 + uu;
    const int ppos = perm32(j);

    // Incremented pointers
    const __half* hrd = d_Hts + kw + tig * 8;                           // += 32768
    __half* hwr = d_Hts + 32768 + (size_t)b_ * 1024 + ppos;             // += 32768
    const float* gxp = d_Gx + (size_t)(b_ * 512) * 4096 + bk * 8 + uu;  // += 4096
    __half* h2p = d_H2h + (size_t)(b_ * 512) * 1024 + bk * 8 + uu;      // += 1024
    unsigned* cntp = d_cnt;                                              // += 1
    const unsigned sfa = (unsigned)__cvta_generic_to_shared(&sflag);

    __syncthreads();   // sflag init + weight preload complete

    // Prefetch Gx for step 0
    float gx0 = 0.f, gx1 = 0.f, gx2 = 0.f, gx3 = 0.f;
    if (is_state) {
        gx0 = __ldcs(gxp);
        gx1 = __ldcs(gxp + 1024);
        gx2 = __ldcs(gxp + 2048);
        gx3 = __ldcs(gxp + 3072);
    }

    for (int t = 0; t < 512; t++) {
        // ---- Per-warp wait on the block's release flag ----
        if (t > 0) {
            unsigned v;
            do {
                asm volatile("ld.acquire.cta.shared.u32 %0, [%1];"
                             : "=r"(v) : "r"(sfa) : "memory");
            } while (v < (unsigned)t);
        }

        // ---- Front-batched h loads: 8 x LDG.128 (max MLP) ----
        uint4 V[2][2][2];   // [kb][mt][row g / g+8]
#pragma unroll
        for (int kb = 0; kb < 2; kb++)
#pragma unroll
            for (int mt = 0; mt < 2; mt++) {
                V[kb][mt][0] = __ldcg((const uint4*)(hrd + kb * 32 + (mt * 16 + g) * 1024));
                V[kb][mt][1] = __ldcg((const uint4*)(hrd + kb * 32 + (mt * 16 + g + 8) * 1024));
            }

        // ---- h_t @ Wh_slice (fp16 HMMA, fp32 accum) ----
        float Cr[2][4][4];
#pragma unroll
        for (int mt = 0; mt < 2; mt++)
#pragma unroll
            for (int nt = 0; nt < 4; nt++)
#pragma unroll
                for (int c = 0; c < 4; c++) Cr[mt][nt][c] = 0.f;

#pragma unroll
        for (int kb = 0; kb < 2; kb++) {
#pragma unroll
            for (int mt = 0; mt < 2; mt++) {
                const uint4& v0 = V[kb][mt][0];
                const uint4& v1 = V[kb][mt][1];
#pragma unroll
                for (int nt = 0; nt < 4; nt++)
                    mma_f16(Cr[mt][nt], v0.x, v1.x, v0.y, v1.y,
                            Wr[2 * kb][nt][0], Wr[2 * kb][nt][1]);
#pragma unroll
                for (int nt = 0; nt < 4; nt++)
                    mma_f16(Cr[mt][nt], v0.z, v1.z, v0.w, v1.w,
                            Wr[2 * kb + 1][nt][0], Wr[2 * kb + 1][nt][1]);
            }
        }

        // ---- Write partials: region w, gate-contiguous layout ----
        {
            float* sp = sPart + w * 1152;
#pragma unroll
            for (int mt = 0; mt < 2; mt++) {
#pragma unroll
                for (int nt = 0; nt < 4; nt++) {
                    int row = mt * 16 + g, c = 2 * tig;
                    sp[row * 36 + c * 4 + nt]             = Cr[mt][nt][0];
                    sp[row * 36 + (c + 1) * 4 + nt]       = Cr[mt][nt][1];
                    sp[(row + 8) * 36 + c * 4 + nt]       = Cr[mt][nt][2];
                    sp[(row + 8) * 36 + (c + 1) * 4 + nt] = Cr[mt][nt][3];
                }
            }
        }

        // ---- Split barrier + state epilogue + arrival + release ----
        if (is_state) {
            asm volatile("bar.sync 3, 512;" ::: "memory");   // all partials in

            const float4* rp = (const float4*)sPart + (b_ * 9 + uu);
            float4 s0 = rp[0], s1 = rp[288];
#pragma unroll
            for (int r = 2; r < 16; r += 2) {
                float4 a = rp[r * 288], b = rp[(r + 1) * 288];
                s0.x += a.x; s0.y += a.y; s0.z += a.z; s0.w += a.w;
                s1.x += b.x; s1.y += b.y; s1.z += b.z; s1.w += b.w;
            }
            float F = s0.x + s1.x + gx0;
            float I = s0.y + s1.y + gx1;
            float G = s0.z + s1.z + gx2;
            float O = s0.w + s1.w + gx3;
            creg = sigm(F) * creg + sigm(I) * tanh_a(G);
            float h = sigm(O) * tanh_a(creg);

            __half hh = __float2half_rn(h);
            *hwr = hh;

            // All state threads done (sPart reads + h store) -> arrive
            asm volatile("bar.sync 1, 256;" ::: "memory");
            if (tid == 0) {
                unsigned ret;
                asm volatile("atom.acq_rel.gpu.add.u32 %0, [%1], %2;"
                             : "=r"(ret) : "l"(cntp), "r"(1u) : "memory");
                if (ret + 1u < NB2) {
                    unsigned v;
                    do {
                        asm volatile("ld.acquire.gpu.u32 %0, [%1];"
                                     : "=r"(v) : "l"(cntp) : "memory");
                    } while (v < NB2);
                }
                asm volatile("st.release.cta.shared.u32 [%0], %1;"
                             :: "r"(sfa), "r"((unsigned)(t + 1)) : "memory");
            }

            // Off the release-drain set: FC-layout h store + Gx prefetch
            *h2p = hh;
            gxp += 4096;
            if (t < 511) {
                gx0 = __ldcs(gxp);
                gx1 = __ldcs(gxp + 1024);
                gx2 = __ldcs(gxp + 2048);
                gx3 = __ldcs(gxp + 3072);
            }
        } else {
            asm volatile("bar.arrive 3, 512;" ::: "memory");
        }

        hrd += 32768; hwr += 32768; h2p += 1024; cntp += 1;
    }
}

// ------------------------------------------------------------------
// Launch sequence (graph-capturable: kernel launches only)
// ------------------------------------------------------------------
extern "C" void kernel_launch(void* const* d_in, const int* in_sizes, int n_in,
                              void* d_out, int out_size) {
    const float* x    = (const float*)d_in[0];
    const float* W_f  = (const float*)d_in[1];
    const float* b_f  = (const float*)d_in[2];
    const float* W_i  = (const float*)d_in[3];
    const float* b_i  = (const float*)d_in[4];
    const float* W_g  = (const float*)d_in[5];
    const float* b_g  = (const float*)d_in[6];
    const float* W_o  = (const float*)d_in[7];
    const float* b_o  = (const float*)d_in[8];
    const float* W_fc = (const float*)d_in[9];
    const float* b_fc = (const float*)d_in[10];
    float* out = (float*)d_out;

    void *pGx, *pH2h, *pXh, *pWxh, *pWfch, *pbx;
    cudaGetSymbolAddress(&pGx, d_Gx);
    cudaGetSymbolAddress(&pH2h, d_H2h);
    cudaGetSymbolAddress(&pXh, d_xh);
    cudaGetSymbolAddress(&pWxh, d_Wxh);
    cudaGetSymbolAddress(&pWfch, d_Wfch);
    cudaGetSymbolAddress(&pbx, d_bx);

    static bool attr_set = false;
    if (!attr_set) {
        cudaFuncSetAttribute(lstm_rec, cudaFuncAttributeMaxDynamicSharedMemorySize,
                             16 * 1152 * 4);
        cudaFuncSetAttribute(gemm_f16_bias, cudaFuncAttributeMaxDynamicSharedMemorySize,
                             GEMM_SMEM);
        attr_set = true;
    }

    // Fused prep: h0/counters + x->fp16 + Wx/W_fc/bias packing
    prep_kernel<<<16384, 256>>>(x, W_f, W_i, W_g, W_o,
                                b_f, b_i, b_g, b_o, W_fc);

    // Phase 1: Gx = x @ Wx + bx   (fp16 HMMA, M=16384, N=4096, K=512)
    gemm_f16_bias<<<dim3(32, 128), 256, GEMM_SMEM>>>(
        (const __half*)pXh, (const __half*)pWxh, (const float*)pbx,
        (float*)pGx, 16384, 4096, 512);

    // Phase 2: recurrence (persistent, 128 blocks)
    lstm_rec<<<NB2, 512, 16 * 1152 * 4>>>(W_f, W_i, W_g, W_o);

    // Phase 3: out = H2h @ W_fc + b_fc   (fp16 HMMA, M=16384, N=512, K=1024)
    gemm_f16_bias<<<dim3(4, 128), 256, GEMM_SMEM>>>(
        (const __half*)pH2h, (const __half*)pWfch, b_fc,
        out, 16384, 512, 1024);
}

// round 16
// speedup vs baseline: 2.9706x; 1.0045x over previous
#include <cuda_runtime.h>
#include <cuda_bf16.h>
#include <cuda_fp16.h>
#include <cstdint>

#define NB2 128   // persistent blocks in recurrent kernel (best measured)

// ------------------------------------------------------------------
// Device-global scratch (allocation-free)
// ------------------------------------------------------------------
__device__ __half d_H2h[(size_t)16384 * 1024];     // h fp16 [b*512+t][j] for final FC
__device__ __half d_Hts[(size_t)513 * 32 * 1024];  // h fp16 [t][b][k_perm]
__device__ __half d_xh[(size_t)512 * 32 * 512];    // x fp16 [t][b][k_perm512]
__device__ __half d_Wfch[(size_t)1024 * 512];      // fp16 W_fc, k-pair interleaved
__device__ unsigned d_cnt[512];                    // per-step arrival counters

// ------------------------------------------------------------------
// Helpers
// ------------------------------------------------------------------
__device__ __forceinline__ void mma_f16(float c[4],
                                        unsigned a0, unsigned a1, unsigned a2, unsigned a3,
                                        unsigned b0, unsigned b1) {
    asm volatile(
        "mma.sync.aligned.m16n8k16.row.col.f32.f16.f16.f32 "
        "{%0,%1,%2,%3},{%4,%5,%6,%7},{%8,%9},{%0,%1,%2,%3};"
        : "+f"(c[0]), "+f"(c[1]), "+f"(c[2]), "+f"(c[3])
        : "r"(a0), "r"(a1), "r"(a2), "r"(a3), "r"(b0), "r"(b1));
}

__device__ __forceinline__ void ldsm_x4(unsigned& r0, unsigned& r1,
                                        unsigned& r2, unsigned& r3,
                                        const __half* p) {
    unsigned addr = (unsigned)__cvta_generic_to_shared(p);
    asm volatile("ldmatrix.sync.aligned.m8n8.x4.shared.b16 {%0,%1,%2,%3}, [%4];"
                 : "=r"(r0), "=r"(r1), "=r"(r2), "=r"(r3) : "r"(addr));
}

__device__ __forceinline__ void cpa16(__half* s, const __half* g) {
    unsigned sa = (unsigned)__cvta_generic_to_shared(s);
    asm volatile("cp.async.ca.shared.global [%0], [%1], 16;" :: "r"(sa), "l"(g));
}

__device__ __forceinline__ float tanh_a(float x) {
    float y;
    asm("tanh.approx.f32 %0, %1;" : "=f"(y) : "f"(x));
    return y;
}
__device__ __forceinline__ float sigm(float x) {
    return 0.5f * tanh_a(0.5f * x) + 0.5f;
}

// k-permutation within 32-element groups (verified R5-R15).
// perm32(2m) is even and perm32(2m+1) = perm32(2m)+1 (pairs stay adjacent).
__device__ __forceinline__ int perm32(int j) {
    int tg = (j & 7) >> 1;
    int a  = (j & 31) >> 4;
    return (j & ~31) + tg * 8 + a * 4 + (j & 1) + 2 * ((j & 15) >> 3);
}

// ------------------------------------------------------------------
// Fused prep: h_0 zero + counters + x -> fp16 [t][b][k_perm512]
// + W_fc pack. Grid 16384 x 256 (covers 4,194,304 x-pairs exactly).
// ------------------------------------------------------------------
__global__ void prep_kernel(const float* __restrict__ x,
                            const float* __restrict__ Wfc) {
    int idx = blockIdx.x * blockDim.x + threadIdx.x;

    {   // x [b][t][k] f32 -> d_xh [t][b][perm32(k)] fp16, pair-wise
        int b = idx >> 17;             // 512*256 pairs per batch row
        int rem = idx & 0x1FFFF;
        int t = rem >> 8;
        int kp = (rem & 255) * 2;
        float2 v = *(const float2*)(x + ((size_t)b * 262144 + t * 512 + kp));
        int dst = t * 16384 + b * 512 + perm32(kp);   // even
        *(__half2*)(d_xh + dst) = __floats2half2_rn(v.x, v.y);
    }
    if (idx < 1024 * 512) {   // W_fc pack, k-pair interleaved
        int k = idx >> 9, j = idx & 511;
        d_Wfch[(((size_t)(k >> 1) * 512) + j) * 2 + (k & 1)] = __float2half_rn(Wfc[idx]);
    }
    if (idx < 16384) ((unsigned*)d_Hts)[idx] = 0u;
    if (idx < 512) d_cnt[idx] = 0u;
}

// ------------------------------------------------------------------
// fp16 GEMM (phase 3 only): C[M,N] = A[M,K] @ B[K,N] + bias[N]
// 128x128x32 tiles, 8 warps; ldmatrix A-frags; 3-stage cp.async ring.
// ------------------------------------------------------------------
#define GEMM_SMEM (3 * (5120 + 4352) * 2)

__global__ void __launch_bounds__(256) gemm_f16_bias(
    const __half* __restrict__ A, const __half* __restrict__ Bp,
    const float* __restrict__ bias, float* __restrict__ C,
    int M, int N, int K) {
    extern __shared__ __half sm[];
    const int tid = threadIdx.x;
    const int w = tid >> 5, lane = tid & 31;
    const int g = lane >> 2, tig = lane & 3;
    const int wm = (w >> 2) * 64, wn = (w & 3) * 32;
    const int m0 = blockIdx.y * 128, n0 = blockIdx.x * 128;

    const int rA = wm + (lane & 7) + ((lane >> 3) & 1) * 8;
    const int cA = ((lane >> 4) & 1) * 8;

    const int arr0 = tid >> 2,           aq0 = tid & 3;
    const int arr1 = (tid + 256) >> 2,   aq1 = tid & 3;
    const int bk0 = tid >> 5,            bc0 = tid & 31;
    const int bk1 = (tid + 256) >> 5,    bc1 = tid & 31;

    const __half* gA0 = A + (size_t)(m0 + arr0) * K + aq0 * 8;
    const __half* gA1 = A + (size_t)(m0 + arr1) * K + aq1 * 8;
    const __half* gB0 = Bp + ((size_t)bk0 * N + n0 + bc0 * 4) * 2;
    const __half* gB1 = Bp + ((size_t)bk1 * N + n0 + bc1 * 4) * 2;

    float Cr[4][4][4];
#pragma unroll
    for (int a = 0; a < 4; a++)
#pragma unroll
        for (int b = 0; b < 4; b++)
#pragma unroll
            for (int c = 0; c < 4; c++) Cr[a][b][c] = 0.f;

    const int nk = K / 32;

    auto issue = [&](int kc) {
        int s = kc % 3;
        __half* sAs = sm + s * 5120;
        __half* sBs = sm + 15360 + s * 4352;
        int k0 = kc * 32;
        cpa16(sAs + arr0 * 40 + aq0 * 8, gA0 + k0);
        cpa16(sAs + arr1 * 40 + aq1 * 8, gA1 + k0);
        cpa16(sBs + bk0 * 272 + bc0 * 8, gB0 + (size_t)(k0 >> 1) * N * 2);
        cpa16(sBs + bk1 * 272 + bc1 * 8, gB1 + (size_t)(k0 >> 1) * N * 2);
        asm volatile("cp.async.commit_group;" ::: "memory");
    };

    issue(0);
    if (nk > 1) issue(1);

    for (int kc = 0; kc < nk; kc++) {
        if (kc + 1 < nk) {
            asm volatile("cp.async.wait_group 1;" ::: "memory");
        } else {
            asm volatile("cp.async.wait_group 0;" ::: "memory");
        }
        __syncthreads();
        if (kc + 2 < nk) issue(kc + 2);

        const int s = kc % 3;
        const __half* sAs = sm + s * 5120;
        const __half* sBs = sm + 15360 + s * 4352;

#pragma unroll
        for (int kt = 0; kt < 2; kt++) {
            unsigned bf_[4][2];
#pragma unroll
            for (int nt = 0; nt < 4; nt++) {
                int jc = wn + nt * 8 + g;
                bf_[nt][0] = *(const unsigned*)(sBs + (kt * 8 + tig) * 272 + jc * 2);
                bf_[nt][1] = *(const unsigned*)(sBs + (kt * 8 + tig + 4) * 272 + jc * 2);
            }
#pragma unroll
            for (int mt = 0; mt < 4; mt++) {
                unsigned a0, a1, a2, a3;
                ldsm_x4(a0, a1, a2, a3,
                        sAs + (rA + mt * 16) * 40 + kt * 16 + cA);
#pragma unroll
                for (int nt = 0; nt < 4; nt++)
                    mma_f16(Cr[mt][nt], a0, a1, a2, a3, bf_[nt][0], bf_[nt][1]);
            }
        }
    }

#pragma unroll
    for (int mt = 0; mt < 4; mt++) {
#pragma unroll
        for (int nt = 0; nt < 4; nt++) {
            int row = m0 + wm + mt * 16 + g;
            int col = n0 + wn + nt * 8 + 2 * tig;
            float bx = bias[col], by = bias[col + 1];
            float2 v0 = make_float2(Cr[mt][nt][0] + bx, Cr[mt][nt][1] + by);
            float2 v1 = make_float2(Cr[mt][nt][2] + bx, Cr[mt][nt][3] + by);
            *(float2*)(C + (size_t)row * N + col) = v0;
            *(float2*)(C + (size_t)(row + 8) * N + col) = v1;
        }
    }
}

// ------------------------------------------------------------------
// Persistent recurrent kernel with FUSED input projection.
// 128 blocks x 512 threads (16 warps). Sync = R14 structure (best).
// Warp w: h K-slice [64w, 64w+64) AND x K-slice [32w, 32w+32).
// The x-part MMAs (no h dependency) run BEFORE the flag poll, so
// they hide in the wait slack. Gate biases live in state-thread regs.
// No d_Gx buffer, no phase-1 GEMM.
// ------------------------------------------------------------------
__global__ void __launch_bounds__(512) lstm_rec(
    const float* __restrict__ Wf, const float* __restrict__ Wi,
    const float* __restrict__ Wg, const float* __restrict__ Wo,
    const float* __restrict__ bf, const float* __restrict__ bi,
    const float* __restrict__ bg, const float* __restrict__ bo) {
    extern __shared__ float sPart[];   // 16 regions x 32 rows x 36 floats
    __shared__ unsigned sflag;

    const int tid = threadIdx.x;
    const int w = tid >> 5, lane = tid & 31;
    const int g = lane >> 2, tig = lane & 3;
    const int kw = w * 64;    // h K-slice base (rows 512.. of W)
    const int kx = w * 32;    // x K-slice base (rows 0..511 of W)
    const int bk = blockIdx.x;

    if (tid == 0) sflag = 0u;

    // ---- Preload recurrent weights Wh as fp16x2 B-fragments ----
    const float* Wp[4] = {Wf, Wi, Wg, Wo};
    unsigned Wr[4][4][2];
#pragma unroll
    for (int kt = 0; kt < 4; kt++) {
#pragma unroll
        for (int nt = 0; nt < 4; nt++) {
            const float* ws = Wp[nt] + (size_t)(512 + kw + kt * 16 + 2 * tig) * 1024 + bk * 8 + g;
            __half2 lo = __floats2half2_rn(__ldg(ws), __ldg(ws + 1024));
            __half2 hi = __floats2half2_rn(__ldg(ws + 8 * 1024), __ldg(ws + 9 * 1024));
            Wr[kt][nt][0] = *(unsigned*)&lo;
            Wr[kt][nt][1] = *(unsigned*)&hi;
        }
    }
    // ---- Preload input-projection weights Wx (rows 0..511) ----
    unsigned Wxr[2][4][2];
#pragma unroll
    for (int kt = 0; kt < 2; kt++) {
#pragma unroll
        for (int nt = 0; nt < 4; nt++) {
            const float* ws = Wp[nt] + (size_t)(kx + kt * 16 + 2 * tig) * 1024 + bk * 8 + g;
            __half2 lo = __floats2half2_rn(__ldg(ws), __ldg(ws + 1024));
            __half2 hi = __floats2half2_rn(__ldg(ws + 8 * 1024), __ldg(ws + 9 * 1024));
            Wxr[kt][nt][0] = *(unsigned*)&lo;
            Wxr[kt][nt][1] = *(unsigned*)&hi;
        }
    }

    // State-thread mapping (first 256 threads): b = tid/8, uu = tid%8
    const int b_ = (tid >> 3) & 31, uu = tid & 7;
    const bool is_state = tid < 256;
    float creg = 0.f;
    const int j = bk * 8 + uu;
    const int ppos = perm32(j);

    // Gate biases in registers (replaces the Gx prefetch entirely)
    float bF = 0.f, bI = 0.f, bG = 0.f, bO = 0.f;
    if (is_state) {
        bF = __ldg(bf + j); bI = __ldg(bi + j);
        bG = __ldg(bg + j); bO = __ldg(bo + j);
    }

    // Incremented pointers
    const __half* hrd = d_Hts + kw + tig * 8;                           // += 32768
    const __half* xrd = d_xh + kx + tig * 8;                            // += 16384
    __half* hwr = d_Hts + 32768 + (size_t)b_ * 1024 + ppos;             // += 32768
    __half* h2p = d_H2h + (size_t)(b_ * 512) * 1024 + bk * 8 + uu;      // += 1024
    unsigned* cntp = d_cnt;                                              // += 1
    const unsigned sfa = (unsigned)__cvta_generic_to_shared(&sflag);

    __syncthreads();   // sflag init + weight preload complete

    for (int t = 0; t < 512; t++) {
        // ---- x-part: x_t @ Wx_slice (NO h dependency; runs pre-poll) ----
        float Cr[2][4][4];
#pragma unroll
        for (int mt = 0; mt < 2; mt++)
#pragma unroll
            for (int nt = 0; nt < 4; nt++)
#pragma unroll
                for (int c = 0; c < 4; c++) Cr[mt][nt][c] = 0.f;

#pragma unroll
        for (int mt = 0; mt < 2; mt++) {
            uint4 u0 = __ldcg((const uint4*)(xrd + (mt * 16 + g) * 512));
            uint4 u1 = __ldcg((const uint4*)(xrd + (mt * 16 + g + 8) * 512));
#pragma unroll
            for (int nt = 0; nt < 4; nt++)
                mma_f16(Cr[mt][nt], u0.x, u1.x, u0.y, u1.y,
                        Wxr[0][nt][0], Wxr[0][nt][1]);
#pragma unroll
            for (int nt = 0; nt < 4; nt++)
                mma_f16(Cr[mt][nt], u0.z, u1.z, u0.w, u1.w,
                        Wxr[1][nt][0], Wxr[1][nt][1]);
        }

        // ---- Per-warp wait on the block's release flag ----
        if (t > 0) {
            unsigned v;
            do {
                asm volatile("ld.acquire.cta.shared.u32 %0, [%1];"
                             : "=r"(v) : "r"(sfa) : "memory");
            } while (v < (unsigned)t);
        }

        // ---- Front-batched h loads: 8 x LDG.128 (max MLP) ----
        uint4 V[2][2][2];   // [kb][mt][row g / g+8]
#pragma unroll
        for (int kb = 0; kb < 2; kb++)
#pragma unroll
            for (int mt = 0; mt < 2; mt++) {
                V[kb][mt][0] = __ldcg((const uint4*)(hrd + kb * 32 + (mt * 16 + g) * 1024));
                V[kb][mt][1] = __ldcg((const uint4*)(hrd + kb * 32 + (mt * 16 + g + 8) * 1024));
            }

        // ---- h_t @ Wh_slice (accumulate into Cr) ----
#pragma unroll
        for (int kb = 0; kb < 2; kb++) {
#pragma unroll
            for (int mt = 0; mt < 2; mt++) {
                const uint4& v0 = V[kb][mt][0];
                const uint4& v1 = V[kb][mt][1];
#pragma unroll
                for (int nt = 0; nt < 4; nt++)
                    mma_f16(Cr[mt][nt], v0.x, v1.x, v0.y, v1.y,
                            Wr[2 * kb][nt][0], Wr[2 * kb][nt][1]);
#pragma unroll
                for (int nt = 0; nt < 4; nt++)
                    mma_f16(Cr[mt][nt], v0.z, v1.z, v0.w, v1.w,
                            Wr[2 * kb + 1][nt][0], Wr[2 * kb + 1][nt][1]);
            }
        }

        // ---- Write partials: region w, gate-contiguous layout ----
        {
            float* sp = sPart + w * 1152;
#pragma unroll
            for (int mt = 0; mt < 2; mt++) {
#pragma unroll
                for (int nt = 0; nt < 4; nt++) {
                    int row = mt * 16 + g, c = 2 * tig;
                    sp[row * 36 + c * 4 + nt]             = Cr[mt][nt][0];
                    sp[row * 36 + (c + 1) * 4 + nt]       = Cr[mt][nt][1];
                    sp[(row + 8) * 36 + c * 4 + nt]       = Cr[mt][nt][2];
                    sp[(row + 8) * 36 + (c + 1) * 4 + nt] = Cr[mt][nt][3];
                }
            }
        }

        // ---- Split barrier + state epilogue + arrival + release ----
        if (is_state) {
            asm volatile("bar.sync 3, 512;" ::: "memory");   // all partials in

            const float4* rp = (const float4*)sPart + (b_ * 9 + uu);
            float4 s0 = rp[0], s1 = rp[288];
#pragma unroll
            for (int r = 2; r < 16; r += 2) {
                float4 a = rp[r * 288], b = rp[(r + 1) * 288];
                s0.x += a.x; s0.y += a.y; s0.z += a.z; s0.w += a.w;
                s1.x += b.x; s1.y += b.y; s1.z += b.z; s1.w += b.w;
            }
            float F = s0.x + s1.x + bF;
            float I = s0.y + s1.y + bI;
            float G = s0.z + s1.z + bG;
            float O = s0.w + s1.w + bO;
            creg = sigm(F) * creg + sigm(I) * tanh_a(G);
            float h = sigm(O) * tanh_a(creg);

            __half hh = __float2half_rn(h);
            *hwr = hh;

            // All state threads done (sPart reads + h store) -> arrive
            asm volatile("bar.sync 1, 256;" ::: "memory");
            if (tid == 0) {
                unsigned ret;
                asm volatile("atom.acq_rel.gpu.add.u32 %0, [%1], %2;"
                             : "=r"(ret) : "l"(cntp), "r"(1u) : "memory");
                if (ret + 1u < NB2) {
                    unsigned v;
                    do {
                        asm volatile("ld.acquire.gpu.u32 %0, [%1];"
                                     : "=r"(v) : "l"(cntp) : "memory");
                    } while (v < NB2);
                }
                asm volatile("st.release.cta.shared.u32 [%0], %1;"
                             :: "r"(sfa), "r"((unsigned)(t + 1)) : "memory");
            }

            // Off the release-drain set: FC-layout h store
            *h2p = hh;
        } else {
            asm volatile("bar.arrive 3, 512;" ::: "memory");
        }

        hrd += 32768; xrd += 16384; hwr += 32768; h2p += 1024; cntp += 1;
    }
}

// ------------------------------------------------------------------
// Launch sequence (graph-capturable: kernel launches only)
// ------------------------------------------------------------------
extern "C" void kernel_launch(void* const* d_in, const int* in_sizes, int n_in,
                              void* d_out, int out_size) {
    const float* x    = (const float*)d_in[0];
    const float* W_f  = (const float*)d_in[1];
    const float* b_f  = (const float*)d_in[2];
    const float* W_i  = (const float*)d_in[3];
    const float* b_i  = (const float*)d_in[4];
    const float* W_g  = (const float*)d_in[5];
    const float* b_g  = (const float*)d_in[6];
    const float* W_o  = (const float*)d_in[7];
    const float* b_o  = (const float*)d_in[8];
    const float* W_fc = (const float*)d_in[9];
    const float* b_fc = (const float*)d_in[10];
    float* out = (float*)d_out;

    void *pH2h, *pWfch;
    cudaGetSymbolAddress(&pH2h, d_H2h);
    cudaGetSymbolAddress(&pWfch, d_Wfch);

    static bool attr_set = false;
    if (!attr_set) {
        cudaFuncSetAttribute(lstm_rec, cudaFuncAttributeMaxDynamicSharedMemorySize,
                             16 * 1152 * 4);
        cudaFuncSetAttribute(gemm_f16_bias, cudaFuncAttributeMaxDynamicSharedMemorySize,
                             GEMM_SMEM);
        attr_set = true;
    }

    // Fused prep: h0/counters + x->fp16 (permuted) + W_fc pack
    prep_kernel<<<16384, 256>>>(x, W_fc);

    // Phase 2 (now first): recurrence with fused input projection
    lstm_rec<<<NB2, 512, 16 * 1152 * 4>>>(W_f, W_i, W_g, W_o,
                                          b_f, b_i, b_g, b_o);

    // Phase 3: out = H2h @ W_fc + b_fc   (fp16 HMMA, M=16384, N=512, K=1024)
    gemm_f16_bias<<<dim3(4, 128), 256, GEMM_SMEM>>>(
        (const __half*)pH2h, (const __half*)pWfch, b_fc,
        out, 16384, 512, 1024);
}